// round 7
// baseline (speedup 1.0000x reference)
#include <cuda_runtime.h>

#define NTOK 50
#define BTOK 3200      // 50*64
#define P2   68        // pitch (float2 units) for sF2/sK2/sG2/sH2; P2 % 16 == 4 -> all frag reads conflict-free
#define PQ   68        // pitch (float units) for sQ; 4g+t4 perm -> conflict-free

// smem (floats): F2 = 64*68*2 = 8704, K2 = 8704, Q = 4352, H-tail = 4352  -> 26112 = 104,448 B
#define SMEM_WORDS (64*P2*2 + 64*P2*2 + 64*PQ + 64*PQ)

__device__ __forceinline__ float tf32f(float x) {
    unsigned u; asm("cvt.rna.tf32.f32 %0, %1;" : "=r"(u) : "f"(x));
    return __uint_as_float(u);
}

__device__ __forceinline__ void mma8(float* d, const unsigned* a, const unsigned* b) {
    asm volatile(
        "mma.sync.aligned.m16n8k8.row.col.f32.tf32.tf32.f32 "
        "{%0,%1,%2,%3}, {%4,%5,%6,%7}, {%8,%9}, {%0,%1,%2,%3};\n"
        : "+f"(d[0]), "+f"(d[1]), "+f"(d[2]), "+f"(d[3])
        : "r"(a[0]), "r"(a[1]), "r"(a[2]), "r"(a[3]), "r"(b[0]), "r"(b[1]));
}

// 3xTF32: acc += Ah*Bh + Al*Bh + Ah*Bl
__device__ __forceinline__ void mma_split(float* acc, const unsigned* ah, const unsigned* al,
                                          const unsigned* bh, const unsigned* bl) {
    mma8(acc, ah, bh);
    mma8(acc, al, bh);
    mma8(acc, ah, bl);
}

#define U(x) __float_as_uint(x)

__global__ __launch_bounds__(256, 2)
void SAM3E_kernel(const float* __restrict__ Fg,
                  const float* __restrict__ Kw,
                  const float* __restrict__ Qw,
                  float* __restrict__ outg)
{
    extern __shared__ float sm[];
    float2* sF2 = (float2*)sm;                 // [64][P2] {hi,lo}; rows 50..63 zero
    float2* sK2 = sF2 + 64 * P2;               // K_w [d][e] {hi,lo}
    float*  sQ  = (float*)(sK2 + 64 * P2);     // Q_w [e][d] tf32-hi only
    float2* sG2 = sK2;                         // G aliases K (after sync)
    float2* sH2 = (float2*)sQ;                 // H aliases Q + tail region

    const int b   = blockIdx.x;
    const int tid = threadIdx.x;
    const float* Fb = Fg + (size_t)b * BTOK;

    // ---- stage + split once ----
    for (int idx = tid; idx < BTOK; idx += 256) {
        int n = idx >> 6, d = idx & 63;
        float v = Fb[idx];
        float h = tf32f(v);
        sF2[n * P2 + d] = make_float2(h, tf32f(v - h));
    }
    for (int idx = tid; idx < 14 * P2; idx += 256)       // zero pad rows 50..63
        sF2[50 * P2 + idx] = make_float2(0.0f, 0.0f);
    for (int idx = tid; idx < 4096; idx += 256) {
        int r = idx >> 6, c = idx & 63;
        float kv = Kw[idx];
        float kh = tf32f(kv);
        sK2[r * P2 + c] = make_float2(kh, tf32f(kv - kh));
        sQ[r * PQ + c]  = tf32f(Qw[idx]);                // single-precision tf32 branch
    }
    __syncthreads();

    const int w    = tid >> 5;
    const int lane = tid & 31;
    const int g    = lane >> 2;        // 0..7
    const int t4   = lane & 3;         // 0..3
    const int m0   = (w >> 1) * 16;    // m-band
    const int n0   = (w & 1) * 32;     // n-half (4 n8-tiles)

    float accG[4][4] = {};
    float accH[4][4] = {};
    float accQ[4][4] = {};

    // ---- Phase A1: G = F^T F   (M=64(d), N=64(d'), K=56(n) zero-padded) ----
    #pragma unroll
    for (int kk = 0; kk < 7; ++kk) {
        const int k0 = kk * 8;
        float2 a0 = sF2[(k0 + t4    ) * P2 + m0 + g    ];
        float2 a1 = sF2[(k0 + t4    ) * P2 + m0 + g + 8];
        float2 a2 = sF2[(k0 + t4 + 4) * P2 + m0 + g    ];
        float2 a3 = sF2[(k0 + t4 + 4) * P2 + m0 + g + 8];
        unsigned ah[4] = {U(a0.x), U(a1.x), U(a2.x), U(a3.x)};
        unsigned al[4] = {U(a0.y), U(a1.y), U(a2.y), U(a3.y)};
        #pragma unroll
        for (int t = 0; t < 4; ++t) {
            const int j0 = n0 + 8 * t;
            float2 b0 = sF2[(k0 + t4    ) * P2 + j0 + g];
            float2 b1 = sF2[(k0 + t4 + 4) * P2 + j0 + g];
            unsigned bh[2] = {U(b0.x), U(b1.x)};
            unsigned bl[2] = {U(b0.y), U(b1.y)};
            mma_split(accG[t], ah, al, bh, bl);
        }
    }

    // ---- Phase A2: H = F @ K_w (3-term) and QF = F @ Q_w^T (1-term) ----
    #pragma unroll
    for (int kk = 0; kk < 8; ++kk) {
        const int k0 = kk * 8;
        float2 a0 = sF2[(m0 + g    ) * P2 + k0 + t4    ];
        float2 a1 = sF2[(m0 + g + 8) * P2 + k0 + t4    ];
        float2 a2 = sF2[(m0 + g    ) * P2 + k0 + t4 + 4];
        float2 a3 = sF2[(m0 + g + 8) * P2 + k0 + t4 + 4];
        unsigned ah[4] = {U(a0.x), U(a1.x), U(a2.x), U(a3.x)};
        unsigned al[4] = {U(a0.y), U(a1.y), U(a2.y), U(a3.y)};
        #pragma unroll
        for (int t = 0; t < 4; ++t) {
            const int j0 = n0 + 8 * t;
            // B_K[k][j] = K_w[k][j]  (type1)
            float2 b0 = sK2[(k0 + t4    ) * P2 + j0 + g];
            float2 b1 = sK2[(k0 + t4 + 4) * P2 + j0 + g];
            unsigned bh[2] = {U(b0.x), U(b1.x)};
            unsigned bl[2] = {U(b0.y), U(b1.y)};
            mma_split(accH[t], ah, al, bh, bl);
            // B_Q[k][j] = Q_w[j][k]  (type2, hi only)
            unsigned bq[2];
            bq[0] = U(sQ[(j0 + g) * PQ + k0 + t4    ]);
            bq[1] = U(sQ[(j0 + g) * PQ + k0 + t4 + 4]);
            mma8(accQ[t], ah, bq);
        }
    }

    __syncthreads();   // all warps done reading sK/sQ -> safe to overwrite with G/H

    // ---- store G, H fragments (pre-split, interleaved {hi,lo}) via STS.128 ----
    #pragma unroll
    for (int t = 0; t < 4; ++t) {
        const int col = n0 + 8 * t + 2 * t4;     // even -> float4-aligned in float2 plane
        #pragma unroll
        for (int half = 0; half < 2; ++half) {
            const int row = m0 + g + 8 * half;
            float g0 = accG[t][2 * half], g1 = accG[t][2 * half + 1];
            float h0 = accH[t][2 * half], h1 = accH[t][2 * half + 1];
            float g0h = tf32f(g0), g1h = tf32f(g1);
            float h0h = tf32f(h0), h1h = tf32f(h1);
            *(float4*)&sG2[row * P2 + col] =
                make_float4(g0h, tf32f(g0 - g0h), g1h, tf32f(g1 - g1h));
            *(float4*)&sH2[row * P2 + col] =
                make_float4(h0h, tf32f(h0 - h0h), h1h, tf32f(h1 - h1h));
        }
    }
    __syncthreads();

    // ---- Phase B: T = H @ G  (M=64(n), N=64(d), K=64(e)) ----
    float accT[4][4] = {};
    #pragma unroll
    for (int kk = 0; kk < 8; ++kk) {
        const int k0 = kk * 8;
        float2 a0 = sH2[(m0 + g    ) * P2 + k0 + t4    ];
        float2 a1 = sH2[(m0 + g + 8) * P2 + k0 + t4    ];
        float2 a2 = sH2[(m0 + g    ) * P2 + k0 + t4 + 4];
        float2 a3 = sH2[(m0 + g + 8) * P2 + k0 + t4 + 4];
        unsigned ah[4] = {U(a0.x), U(a1.x), U(a2.x), U(a3.x)};
        unsigned al[4] = {U(a0.y), U(a1.y), U(a2.y), U(a3.y)};
        #pragma unroll
        for (int t = 0; t < 4; ++t) {
            const int j0 = n0 + 8 * t;
            float2 b0 = sG2[(k0 + t4    ) * P2 + j0 + g];
            float2 b1 = sG2[(k0 + t4 + 4) * P2 + j0 + g];
            unsigned bh[2] = {U(b0.x), U(b1.x)};
            unsigned bl[2] = {U(b0.y), U(b1.y)};
            mma_split(accT[t], ah, al, bh, bl);
        }
    }

    // ---- Epilogue: out = F .* T + QF  (rows < 50 only; F = hi + lo) ----
    float* ob = outg + (size_t)b * BTOK;
    const int r1 = m0 + g;
    const int r2 = m0 + g + 8;
    #pragma unroll
    for (int t = 0; t < 4; ++t) {
        const int col = n0 + 8 * t + 2 * t4;
        if (r1 < NTOK) {
            float4 f = *(const float4*)&sF2[r1 * P2 + col];   // {hi0,lo0,hi1,lo1}
            float2 o;
            o.x = (f.x + f.y) * accT[t][0] + accQ[t][0];
            o.y = (f.z + f.w) * accT[t][1] + accQ[t][1];
            *(float2*)&ob[r1 * 64 + col] = o;
        }
        if (r2 < NTOK) {
            float4 f = *(const float4*)&sF2[r2 * P2 + col];
            float2 o;
            o.x = (f.x + f.y) * accT[t][2] + accQ[t][2];
            o.y = (f.z + f.w) * accT[t][3] + accQ[t][3];
            *(float2*)&ob[r2 * 64 + col] = o;
        }
    }
}

extern "C" void kernel_launch(void* const* d_in, const int* in_sizes, int n_in,
                              void* d_out, int out_size)
{
    const float* F  = (const float*)d_in[0];
    const float* Kw = (const float*)d_in[1];
    const float* Qw = (const float*)d_in[2];
    float* out      = (float*)d_out;

    const int B = in_sizes[0] / BTOK;                       // 8192
    const int smem_bytes = SMEM_WORDS * sizeof(float);      // 104,448 B

    cudaFuncSetAttribute(SAM3E_kernel,
                         cudaFuncAttributeMaxDynamicSharedMemorySize, smem_bytes);

    SAM3E_kernel<<<B, 256, smem_bytes>>>(F, Kw, Qw, out);
}

// round 8
// speedup vs baseline: 2.4661x; 2.4661x over previous
#include <cuda_runtime.h>
#include <cuda_bf16.h>

#define NTOK 50
#define BTOK 3200
#define P    72                 // plane pitch in bf16 elems (144 B rows, 16B-aligned, LDSM conflict-free)
#define PB   (P*2)              // 144 bytes
#define PLANE_E (64*P)          // elems per plane
#define PLANE_B (64*PB)         // 9216 bytes per plane

// plane byte offsets in dynamic smem: Fh Fl Kh Kl Qh Ql Gh Gl  (H aliases Q after barrier)
#define OFF_FH 0
#define OFF_FL (1*PLANE_B)
#define OFF_KH (2*PLANE_B)
#define OFF_KL (3*PLANE_B)
#define OFF_QH (4*PLANE_B)
#define OFF_QL (5*PLANE_B)
#define OFF_GH (6*PLANE_B)
#define OFF_GL (7*PLANE_B)
#define OFF_HH OFF_QH
#define OFF_HL OFF_QL
#define SMEM_BYTES (8*PLANE_B)  // 73,728 B -> 3 CTAs/SM

__device__ __forceinline__ void ldsm_x4(unsigned* r, unsigned a) {
    asm volatile("ldmatrix.sync.aligned.m8n8.x4.shared.b16 {%0,%1,%2,%3}, [%4];"
                 : "=r"(r[0]), "=r"(r[1]), "=r"(r[2]), "=r"(r[3]) : "r"(a));
}
__device__ __forceinline__ void ldsm_x4t(unsigned* r, unsigned a) {
    asm volatile("ldmatrix.sync.aligned.m8n8.x4.trans.shared.b16 {%0,%1,%2,%3}, [%4];"
                 : "=r"(r[0]), "=r"(r[1]), "=r"(r[2]), "=r"(r[3]) : "r"(a));
}
__device__ __forceinline__ void ldsm_x2(unsigned* r, unsigned a) {
    asm volatile("ldmatrix.sync.aligned.m8n8.x2.shared.b16 {%0,%1}, [%2];"
                 : "=r"(r[0]), "=r"(r[1]) : "r"(a));
}
__device__ __forceinline__ void ldsm_x2t(unsigned* r, unsigned a) {
    asm volatile("ldmatrix.sync.aligned.m8n8.x2.trans.shared.b16 {%0,%1}, [%2];"
                 : "=r"(r[0]), "=r"(r[1]) : "r"(a));
}
__device__ __forceinline__ void mma16(float* d, const unsigned* a, const unsigned* b) {
    asm volatile(
        "mma.sync.aligned.m16n8k16.row.col.f32.bf16.bf16.f32 "
        "{%0,%1,%2,%3}, {%4,%5,%6,%7}, {%8,%9}, {%0,%1,%2,%3};\n"
        : "+f"(d[0]), "+f"(d[1]), "+f"(d[2]), "+f"(d[3])
        : "r"(a[0]), "r"(a[1]), "r"(a[2]), "r"(a[3]), "r"(b[0]), "r"(b[1]));
}

// split fp32 -> bf16 hi + bf16 lo (lo = bf16(x - hi))
__device__ __forceinline__ void bsplit(float x, __nv_bfloat16& h, __nv_bfloat16& l) {
    h = __float2bfloat16_rn(x);
    l = __float2bfloat16_rn(x - __bfloat162float(h));
}

__global__ __launch_bounds__(256, 3)
void SAM3E_kernel(const float* __restrict__ Fg,
                  const float* __restrict__ Kw,
                  const float* __restrict__ Qw,
                  float* __restrict__ outg)
{
    extern __shared__ __nv_bfloat16 sb[];
    const unsigned sbase = (unsigned)__cvta_generic_to_shared(sb);
    __nv_bfloat16* sFh = sb;
    __nv_bfloat16* sFl = sb + 1*PLANE_E;
    __nv_bfloat16* sKh = sb + 2*PLANE_E;
    __nv_bfloat16* sKl = sb + 3*PLANE_E;
    __nv_bfloat16* sQh = sb + 4*PLANE_E;
    __nv_bfloat16* sQl = sb + 5*PLANE_E;
    __nv_bfloat16* sGh = sb + 6*PLANE_E;
    __nv_bfloat16* sGl = sb + 7*PLANE_E;
    __nv_bfloat16* sHh = sQh;      // aliases Q after mid barrier
    __nv_bfloat16* sHl = sQl;

    const int b   = blockIdx.x;
    const int tid = threadIdx.x;

    // ---- stage: split fp32 inputs once into bf16 hi/lo planes ----
    const float2* Fb2 = (const float2*)(Fg + (size_t)b * BTOK);
    for (int i = tid; i < 1600; i += 256) {            // F rows 0..49
        float2 v = Fb2[i];
        int n = i >> 5, d = (i & 31) << 1;
        __nv_bfloat16 hx, lx, hy, ly;
        bsplit(v.x, hx, lx);  bsplit(v.y, hy, ly);
        *(__nv_bfloat162*)&sFh[n * P + d] = __halves2bfloat162(hx, hy);
        *(__nv_bfloat162*)&sFl[n * P + d] = __halves2bfloat162(lx, ly);
    }
    for (int i = tid; i < 14 * (P / 2); i += 256) {    // zero-pad rows 50..63
        int off = 50 * P + 2 * i;
        *(unsigned*)&sFh[off] = 0u;
        *(unsigned*)&sFl[off] = 0u;
    }
    const float2* K2 = (const float2*)Kw;
    const float2* Q2 = (const float2*)Qw;
    for (int i = tid; i < 2048; i += 256) {            // K_w [d][e], Q_w [e][d] natural
        int r = i >> 5, c = (i & 31) << 1;
        float2 v = K2[i];
        __nv_bfloat16 hx, lx, hy, ly;
        bsplit(v.x, hx, lx);  bsplit(v.y, hy, ly);
        *(__nv_bfloat162*)&sKh[r * P + c] = __halves2bfloat162(hx, hy);
        *(__nv_bfloat162*)&sKl[r * P + c] = __halves2bfloat162(lx, ly);
        float2 u = Q2[i];
        bsplit(u.x, hx, lx);  bsplit(u.y, hy, ly);
        *(__nv_bfloat162*)&sQh[r * P + c] = __halves2bfloat162(hx, hy);
        *(__nv_bfloat162*)&sQl[r * P + c] = __halves2bfloat162(lx, ly);
    }
    __syncthreads();

    const int lane = tid & 31, w = tid >> 5;
    const int m0 = (w >> 1) * 16;           // 16-row band
    const int n0 = (w & 1) * 32;            // 32-col half (4 n8-tiles)
    const int q   = lane & 7;
    const int b8  = (lane >> 3) & 1;
    const int b16 = (lane >> 4) & 1;
    const int g   = lane >> 2, t4 = lane & 3;

    // ================= Phase A1: G = F^T F  (M=d, N=d', K=tokens 64-padded) =================
    float accG[4][4] = {};
    {
        // A = F^T (trans ldsm on F [n][d]); B = F^T too (trans x2)
        const unsigned a1 = sbase + OFF_FH + 2u * ((8 * b16 + q) * P + m0 + 8 * b8);
        const unsigned b1 = sbase + OFF_FH + 2u * ((8 * b8 + q) * P + n0);
        #pragma unroll
        for (int kk = 0; kk < 4; ++kk) {
            unsigned ah[4], al[4];
            ldsm_x4t(ah, a1 + kk * 16 * PB);
            ldsm_x4t(al, a1 + kk * 16 * PB + PLANE_B);
            #pragma unroll
            for (int t = 0; t < 4; ++t) {
                unsigned bh[2], bl[2];
                ldsm_x2t(bh, b1 + kk * 16 * PB + t * 16);
                ldsm_x2t(bl, b1 + kk * 16 * PB + t * 16 + PLANE_B);
                mma16(accG[t], ah, bh);
                mma16(accG[t], al, bh);
                mma16(accG[t], ah, bl);
            }
        }
    }
    // store G tile now (own region, own tile -> no barrier needed yet); frees accG regs
    #pragma unroll
    for (int t = 0; t < 4; ++t) {
        const int col = n0 + 8 * t + 2 * t4;
        float v0 = accG[t][0], v1 = accG[t][1], v2 = accG[t][2], v3 = accG[t][3];
        __nv_bfloat16 h0, l0, h1, l1, h2, l2, h3, l3;
        bsplit(v0, h0, l0); bsplit(v1, h1, l1); bsplit(v2, h2, l2); bsplit(v3, h3, l3);
        *(__nv_bfloat162*)&sGh[(m0 + g    ) * P + col] = __halves2bfloat162(h0, h1);
        *(__nv_bfloat162*)&sGl[(m0 + g    ) * P + col] = __halves2bfloat162(l0, l1);
        *(__nv_bfloat162*)&sGh[(m0 + g + 8) * P + col] = __halves2bfloat162(h2, h3);
        *(__nv_bfloat162*)&sGl[(m0 + g + 8) * P + col] = __halves2bfloat162(l2, l3);
    }

    // ========== Phase A2: H = F @ K_w  and  QF = F @ Q_w^T  (M=n, N=e, K=d) ==========
    float accH[4][4] = {};
    float accQ[4][4] = {};
    {
        const unsigned a2 = sbase + OFF_FH + 2u * ((m0 + 8 * b8 + q) * P + 8 * b16);
        const unsigned bk = sbase + OFF_KH + 2u * ((8 * b8 + q) * P + n0);      // trans: K_w [d][e]
        const unsigned bq = sbase + OFF_QH + 2u * ((n0 + q) * P + 8 * b8);      // non-trans: Q_w [e][d]
        #pragma unroll
        for (int kk = 0; kk < 4; ++kk) {
            unsigned ah[4], al[4];
            ldsm_x4(ah, a2 + kk * 32);
            ldsm_x4(al, a2 + kk * 32 + PLANE_B);
            #pragma unroll
            for (int t = 0; t < 4; ++t) {
                unsigned bh[2], bl[2];
                ldsm_x2t(bh, bk + kk * 16 * PB + t * 16);
                ldsm_x2t(bl, bk + kk * 16 * PB + t * 16 + PLANE_B);
                mma16(accH[t], ah, bh);
                mma16(accH[t], al, bh);
                mma16(accH[t], ah, bl);
                ldsm_x2(bh, bq + kk * 32 + t * 8 * PB);
                ldsm_x2(bl, bq + kk * 32 + t * 8 * PB + PLANE_B);
                mma16(accQ[t], ah, bh);
                mma16(accQ[t], al, bh);
                mma16(accQ[t], ah, bl);
            }
        }
    }
    __syncthreads();   // everyone done reading K/Q; G stores visible

    // store H into the (now dead) Q region
    #pragma unroll
    for (int t = 0; t < 4; ++t) {
        const int col = n0 + 8 * t + 2 * t4;
        float v0 = accH[t][0], v1 = accH[t][1], v2 = accH[t][2], v3 = accH[t][3];
        __nv_bfloat16 h0, l0, h1, l1, h2, l2, h3, l3;
        bsplit(v0, h0, l0); bsplit(v1, h1, l1); bsplit(v2, h2, l2); bsplit(v3, h3, l3);
        *(__nv_bfloat162*)&sHh[(m0 + g    ) * P + col] = __halves2bfloat162(h0, h1);
        *(__nv_bfloat162*)&sHl[(m0 + g    ) * P + col] = __halves2bfloat162(l0, l1);
        *(__nv_bfloat162*)&sHh[(m0 + g + 8) * P + col] = __halves2bfloat162(h2, h3);
        *(__nv_bfloat162*)&sHl[(m0 + g + 8) * P + col] = __halves2bfloat162(l2, l3);
    }
    __syncthreads();

    // ================= Phase B: T = H @ G  (M=n, N=d, K=e; B uses G symmetry) =================
    float accT[4][4] = {};
    {
        const unsigned a3 = sbase + OFF_HH + 2u * ((m0 + 8 * b8 + q) * P + 8 * b16);
        const unsigned b3 = sbase + OFF_GH + 2u * ((n0 + q) * P + 8 * b8);      // non-trans: G [d][e]
        #pragma unroll
        for (int kk = 0; kk < 4; ++kk) {
            unsigned ah[4], al[4];
            ldsm_x4(ah, a3 + kk * 32);
            ldsm_x4(al, a3 + kk * 32 + PLANE_B);
            #pragma unroll
            for (int t = 0; t < 4; ++t) {
                unsigned bh[2], bl[2];
                ldsm_x2(bh, b3 + kk * 32 + t * 8 * PB);
                ldsm_x2(bl, b3 + kk * 32 + t * 8 * PB + PLANE_B);
                mma16(accT[t], ah, bh);
                mma16(accT[t], al, bh);
                mma16(accT[t], ah, bl);
            }
        }
    }

    // ================= Epilogue: out = F .* T + QF  (rows < 50) =================
    float* ob = outg + (size_t)b * BTOK;
    const int r1 = m0 + g;
    const int r2 = m0 + g + 8;
    #pragma unroll
    for (int t = 0; t < 4; ++t) {
        const int col = n0 + 8 * t + 2 * t4;
        if (r1 < NTOK) {
            float2 fh = __bfloat1622float2(*(__nv_bfloat162*)&sFh[r1 * P + col]);
            float2 fl = __bfloat1622float2(*(__nv_bfloat162*)&sFl[r1 * P + col]);
            float2 o;
            o.x = (fh.x + fl.x) * accT[t][0] + accQ[t][0];
            o.y = (fh.y + fl.y) * accT[t][1] + accQ[t][1];
            *(float2*)&ob[r1 * 64 + col] = o;
        }
        if (r2 < NTOK) {
            float2 fh = __bfloat1622float2(*(__nv_bfloat162*)&sFh[r2 * P + col]);
            float2 fl = __bfloat1622float2(*(__nv_bfloat162*)&sFl[r2 * P + col]);
            float2 o;
            o.x = (fh.x + fl.x) * accT[t][2] + accQ[t][2];
            o.y = (fh.y + fl.y) * accT[t][3] + accQ[t][3];
            *(float2*)&ob[r2 * 64 + col] = o;
        }
    }
}

extern "C" void kernel_launch(void* const* d_in, const int* in_sizes, int n_in,
                              void* d_out, int out_size)
{
    const float* F  = (const float*)d_in[0];
    const float* Kw = (const float*)d_in[1];
    const float* Qw = (const float*)d_in[2];
    float* out      = (float*)d_out;

    const int B = in_sizes[0] / BTOK;                   // 8192

    cudaFuncSetAttribute(SAM3E_kernel,
                         cudaFuncAttributeMaxDynamicSharedMemorySize, SMEM_BYTES);

    SAM3E_kernel<<<B, 256, SMEM_BYTES>>>(F, Kw, Qw, out);
}

// round 9
// speedup vs baseline: 3.1425x; 1.2743x over previous
#include <cuda_runtime.h>
#include <cuda_bf16.h>

#define NTOK 50
#define BTOK 3200
#define P    72                 // plane pitch in bf16 elems (144B rows; LDSM conflict-free)
#define PB   (P*2)              // 144 bytes
#define PLANE_E (64*P)
#define PLANE_B (64*PB)         // 9216 B

// 6 planes: Fh Fl Kh Kl Qh X ; G aliases Kh/Kl, H aliases Qh/X (after barriers)
#define OFF_FH 0
#define OFF_FL (1*PLANE_B)
#define OFF_KH (2*PLANE_B)      // -> Gh
#define OFF_KL (3*PLANE_B)      // -> Gl
#define OFF_QH (4*PLANE_B)      // -> Hh
#define OFF_X  (5*PLANE_B)      // -> Hl
#define SMEM_BYTES (6*PLANE_B)  // 55,296 B -> 4 CTAs/SM

__device__ __forceinline__ void ldsm_x4(unsigned* r, unsigned a) {
    asm volatile("ldmatrix.sync.aligned.m8n8.x4.shared.b16 {%0,%1,%2,%3}, [%4];"
                 : "=r"(r[0]), "=r"(r[1]), "=r"(r[2]), "=r"(r[3]) : "r"(a));
}
__device__ __forceinline__ void ldsm_x4t(unsigned* r, unsigned a) {
    asm volatile("ldmatrix.sync.aligned.m8n8.x4.trans.shared.b16 {%0,%1,%2,%3}, [%4];"
                 : "=r"(r[0]), "=r"(r[1]), "=r"(r[2]), "=r"(r[3]) : "r"(a));
}
__device__ __forceinline__ void mma16(float* d, const unsigned* a, const unsigned* b) {
    asm volatile(
        "mma.sync.aligned.m16n8k16.row.col.f32.bf16.bf16.f32 "
        "{%0,%1,%2,%3}, {%4,%5,%6,%7}, {%8,%9}, {%0,%1,%2,%3};\n"
        : "+f"(d[0]), "+f"(d[1]), "+f"(d[2]), "+f"(d[3])
        : "r"(a[0]), "r"(a[1]), "r"(a[2]), "r"(a[3]), "r"(b[0]), "r"(b[1]));
}
__device__ __forceinline__ void bsplit(float x, __nv_bfloat16& h, __nv_bfloat16& l) {
    h = __float2bfloat16_rn(x);
    l = __float2bfloat16_rn(x - __bfloat162float(h));
}

__global__ __launch_bounds__(256, 4)
void SAM3E_kernel(const float* __restrict__ Fg,
                  const float* __restrict__ Kw,
                  const float* __restrict__ Qw,
                  float* __restrict__ outg)
{
    extern __shared__ __nv_bfloat16 sb[];
    const unsigned sbase = (unsigned)__cvta_generic_to_shared(sb);
    __nv_bfloat16* sFh = sb;
    __nv_bfloat16* sFl = sb + 1*PLANE_E;
    __nv_bfloat16* sKh = sb + 2*PLANE_E;
    __nv_bfloat16* sKl = sb + 3*PLANE_E;
    __nv_bfloat16* sQh = sb + 4*PLANE_E;
    __nv_bfloat16* sXp = sb + 5*PLANE_E;
    __nv_bfloat16* sGh = sKh;   // after sync1
    __nv_bfloat16* sGl = sKl;
    __nv_bfloat16* sHh = sQh;   // after sync1
    __nv_bfloat16* sHl = sXp;

    const int b   = blockIdx.x;
    const int tid = threadIdx.x;

    // ---- stage: split fp32 inputs once into bf16 hi/lo planes ----
    const float2* Fb2 = (const float2*)(Fg + (size_t)b * BTOK);
    for (int i = tid; i < 1600; i += 256) {
        float2 v = Fb2[i];
        int n = i >> 5, d = (i & 31) << 1;
        __nv_bfloat16 hx, lx, hy, ly;
        bsplit(v.x, hx, lx);  bsplit(v.y, hy, ly);
        *(__nv_bfloat162*)&sFh[n * P + d] = __halves2bfloat162(hx, hy);
        *(__nv_bfloat162*)&sFl[n * P + d] = __halves2bfloat162(lx, ly);
    }
    for (int i = tid; i < 14 * (P / 2); i += 256) {     // zero-pad rows 50..63
        int off = 50 * P + 2 * i;
        *(unsigned*)&sFh[off] = 0u;
        *(unsigned*)&sFl[off] = 0u;
    }
    const float2* K2 = (const float2*)Kw;
    const float2* Q2 = (const float2*)Qw;
    for (int i = tid; i < 2048; i += 256) {
        int r = i >> 5, c = (i & 31) << 1;
        float2 v = K2[i];
        __nv_bfloat16 hx, lx, hy, ly;
        bsplit(v.x, hx, lx);  bsplit(v.y, hy, ly);
        *(__nv_bfloat162*)&sKh[r * P + c] = __halves2bfloat162(hx, hy);
        *(__nv_bfloat162*)&sKl[r * P + c] = __halves2bfloat162(lx, ly);
        float2 u = Q2[i];                               // Q: hi-only (1-term branch)
        *(__nv_bfloat162*)&sQh[r * P + c] =
            __halves2bfloat162(__float2bfloat16_rn(u.x), __float2bfloat16_rn(u.y));
    }
    __syncthreads();

    const int lane = tid & 31, w = tid >> 5;
    const int m0 = (w >> 1) * 16;           // 16-row band
    const int n0 = (w & 1) * 32;            // 32-col half (4 n8-tiles)
    const int q   = lane & 7;
    const int b8  = (lane >> 3) & 1;
    const int b16 = (lane >> 4) & 1;
    const int g   = lane >> 2, t4 = lane & 3;

    // ========== Phase A2 first: H = F @ K_w (3-term), QF = F @ Q_w^T (1-term) ==========
    float accH[4][4] = {};
    float accQ[4][4] = {};
    {
        const unsigned a2 = sbase + OFF_FH + 2u * ((m0 + 8 * b8 + q) * P + 8 * b16);
        // trans B on K_w [d][e]: x4 covers two n8-tiles (b16 selects tile within pair)
        const unsigned bk = sbase + OFF_KH + 2u * ((8 * b8 + q) * P + n0 + 8 * b16);
        // non-trans B on Q_w [e][d]: x4 covers two n8-tiles
        const unsigned bq = sbase + OFF_QH + 2u * ((n0 + q + 8 * b16) * P + 8 * b8);
        #pragma unroll
        for (int kk = 0; kk < 4; ++kk) {
            unsigned ah[4], al[4];
            ldsm_x4(ah, a2 + kk * 32);
            ldsm_x4(al, a2 + kk * 32 + PLANE_B);
            #pragma unroll
            for (int p = 0; p < 2; ++p) {
                unsigned bh[4], bl[4];
                ldsm_x4t(bh, bk + kk * 16 * PB + p * 32);
                ldsm_x4t(bl, bk + kk * 16 * PB + p * 32 + PLANE_B);
                mma16(accH[2*p  ], ah, bh    );
                mma16(accH[2*p  ], al, bh    );
                mma16(accH[2*p  ], ah, bl    );
                mma16(accH[2*p+1], ah, bh + 2);
                mma16(accH[2*p+1], al, bh + 2);
                mma16(accH[2*p+1], ah, bl + 2);
                unsigned bq4[4];
                ldsm_x4(bq4, bq + kk * 32 + p * 16 * PB);
                mma16(accQ[2*p  ], ah, bq4    );
                mma16(accQ[2*p+1], ah, bq4 + 2);
            }
        }
    }
    __syncthreads();   // all K/Q reads done -> K/Q regions reusable

    // store H (split) into Q-region planes
    #pragma unroll
    for (int t = 0; t < 4; ++t) {
        const int col = n0 + 8 * t + 2 * t4;
        __nv_bfloat16 h0,l0,h1,l1,h2,l2,h3,l3;
        bsplit(accH[t][0],h0,l0); bsplit(accH[t][1],h1,l1);
        bsplit(accH[t][2],h2,l2); bsplit(accH[t][3],h3,l3);
        *(__nv_bfloat162*)&sHh[(m0 + g    ) * P + col] = __halves2bfloat162(h0, h1);
        *(__nv_bfloat162*)&sHl[(m0 + g    ) * P + col] = __halves2bfloat162(l0, l1);
        *(__nv_bfloat162*)&sHh[(m0 + g + 8) * P + col] = __halves2bfloat162(h2, h3);
        *(__nv_bfloat162*)&sHl[(m0 + g + 8) * P + col] = __halves2bfloat162(l2, l3);
    }

    // ========== Phase A1: G = F^T F (reads F only), store into K-region ==========
    {
        float accG[4][4] = {};
        const unsigned a1 = sbase + OFF_FH + 2u * ((8 * b16 + q) * P + m0 + 8 * b8);
        const unsigned b1 = sbase + OFF_FH + 2u * ((8 * b8 + q) * P + n0 + 8 * b16);
        #pragma unroll
        for (int kk = 0; kk < 4; ++kk) {
            unsigned ah[4], al[4];
            ldsm_x4t(ah, a1 + kk * 16 * PB);
            ldsm_x4t(al, a1 + kk * 16 * PB + PLANE_B);
            #pragma unroll
            for (int p = 0; p < 2; ++p) {
                unsigned bh[4], bl[4];
                ldsm_x4t(bh, b1 + kk * 16 * PB + p * 32);
                ldsm_x4t(bl, b1 + kk * 16 * PB + p * 32 + PLANE_B);
                mma16(accG[2*p  ], ah, bh    );
                mma16(accG[2*p  ], al, bh    );
                mma16(accG[2*p  ], ah, bl    );
                mma16(accG[2*p+1], ah, bh + 2);
                mma16(accG[2*p+1], al, bh + 2);
                mma16(accG[2*p+1], ah, bl + 2);
            }
        }
        #pragma unroll
        for (int t = 0; t < 4; ++t) {
            const int col = n0 + 8 * t + 2 * t4;
            __nv_bfloat16 h0,l0,h1,l1,h2,l2,h3,l3;
            bsplit(accG[t][0],h0,l0); bsplit(accG[t][1],h1,l1);
            bsplit(accG[t][2],h2,l2); bsplit(accG[t][3],h3,l3);
            *(__nv_bfloat162*)&sGh[(m0 + g    ) * P + col] = __halves2bfloat162(h0, h1);
            *(__nv_bfloat162*)&sGl[(m0 + g    ) * P + col] = __halves2bfloat162(l0, l1);
            *(__nv_bfloat162*)&sGh[(m0 + g + 8) * P + col] = __halves2bfloat162(h2, h3);
            *(__nv_bfloat162*)&sGl[(m0 + g + 8) * P + col] = __halves2bfloat162(l2, l3);
        }
    }
    __syncthreads();   // G + H stores visible

    // ========== Phase B: T = H @ G  (B reads G rows via symmetry, non-trans) ==========
    float accT[4][4] = {};
    {
        const unsigned a3 = sbase + OFF_QH + 2u * ((m0 + 8 * b8 + q) * P + 8 * b16);  // H planes
        const unsigned b3 = sbase + OFF_KH + 2u * ((n0 + q + 8 * b16) * P + 8 * b8);  // G planes
        #pragma unroll
        for (int kk = 0; kk < 4; ++kk) {
            unsigned ah[4], al[4];
            ldsm_x4(ah, a3 + kk * 32);
            ldsm_x4(al, a3 + kk * 32 + PLANE_B);
            #pragma unroll
            for (int p = 0; p < 2; ++p) {
                unsigned bh[4], bl[4];
                ldsm_x4(bh, b3 + kk * 32 + p * 16 * PB);
                ldsm_x4(bl, b3 + kk * 32 + p * 16 * PB + PLANE_B);
                mma16(accT[2*p  ], ah, bh    );
                mma16(accT[2*p  ], al, bh    );
                mma16(accT[2*p  ], ah, bl    );
                mma16(accT[2*p+1], ah, bh + 2);
                mma16(accT[2*p+1], al, bh + 2);
                mma16(accT[2*p+1], ah, bl + 2);
            }
        }
    }

    // ========== Epilogue: out = F .* T + QF  (rows < 50) ==========
    float* ob = outg + (size_t)b * BTOK;
    const int r1 = m0 + g;
    const int r2 = m0 + g + 8;
    #pragma unroll
    for (int t = 0; t < 4; ++t) {
        const int col = n0 + 8 * t + 2 * t4;
        if (r1 < NTOK) {
            float2 fh = __bfloat1622float2(*(__nv_bfloat162*)&sFh[r1 * P + col]);
            float2 fl = __bfloat1622float2(*(__nv_bfloat162*)&sFl[r1 * P + col]);
            float2 o;
            o.x = (fh.x + fl.x) * accT[t][0] + accQ[t][0];
            o.y = (fh.y + fl.y) * accT[t][1] + accQ[t][1];
            *(float2*)&ob[r1 * 64 + col] = o;
        }
        if (r2 < NTOK) {
            float2 fh = __bfloat1622float2(*(__nv_bfloat162*)&sFh[r2 * P + col]);
            float2 fl = __bfloat1622float2(*(__nv_bfloat162*)&sFl[r2 * P + col]);
            float2 o;
            o.x = (fh.x + fl.x) * accT[t][2] + accQ[t][2];
            o.y = (fh.y + fl.y) * accT[t][3] + accQ[t][3];
            *(float2*)&ob[r2 * 64 + col] = o;
        }
    }
}

extern "C" void kernel_launch(void* const* d_in, const int* in_sizes, int n_in,
                              void* d_out, int out_size)
{
    const float* F  = (const float*)d_in[0];
    const float* Kw = (const float*)d_in[1];
    const float* Qw = (const float*)d_in[2];
    float* out      = (float*)d_out;

    const int B = in_sizes[0] / BTOK;                   // 8192

    cudaFuncSetAttribute(SAM3E_kernel,
                         cudaFuncAttributeMaxDynamicSharedMemorySize, SMEM_BYTES);

    SAM3E_kernel<<<B, 256, SMEM_BYTES>>>(F, Kw, Qw, out);
}